// round 15
// baseline (speedup 1.0000x reference)
#include <cuda_runtime.h>
#include <cuda_bf16.h>
#include <cstdint>

// Problem constants
#define BB 32
#define NN 2048
#define DD 128
#define HH 8
#define KQ 64
#define NSPLIT 8

// ------------------------------------------------------------------ scratch
__device__ float g_Spart[NSPLIT * BB * DD * DD];     // gram partials (fp32)
__device__ float g_S[BB * DD * DD];                  // summed S, tf32-rounded
__device__ float g_Mpart[HH * BB * DD * DD];         // M partials per head
__device__ float g_M[BB * DD * DD];                  // summed M, tf32-rounded

// ------------------------------------------------------------------ helpers
__device__ __forceinline__ uint32_t smem_u32(const void* p) {
    uint32_t a;
    asm("{ .reg .u64 t; cvta.to.shared.u64 t, %1; cvt.u32.u64 %0, t; }"
        : "=r"(a) : "l"(p));
    return a;
}

#define GRIDDEP_WAIT() asm volatile("griddepcontrol.wait;" ::: "memory")

#define CP_ASYNC16(saddr, gptr) \
    asm volatile("cp.async.cg.shared.global [%0], [%1], 16;" \
                 :: "r"(saddr), "l"(gptr) : "memory")
#define CP_ASYNC_COMMIT() asm volatile("cp.async.commit_group;" ::: "memory")
#define CP_ASYNC_WAIT0()  asm volatile("cp.async.wait_group 0;" ::: "memory")
#define CP_ASYNC_WAIT1()  asm volatile("cp.async.wait_group 1;" ::: "memory")

__device__ __forceinline__ void ldsm4(uint32_t* r, uint32_t addr) {
    asm volatile("ldmatrix.sync.aligned.m8n8.x4.shared.b16 {%0,%1,%2,%3}, [%4];"
                 : "=r"(r[0]), "=r"(r[1]), "=r"(r[2]), "=r"(r[3]) : "r"(addr));
}

__device__ __forceinline__ void mma_tf32(float* d, const uint32_t* a,
                                         uint32_t b0, uint32_t b1) {
    asm volatile(
        "mma.sync.aligned.m16n8k8.row.col.f32.tf32.tf32.f32 "
        "{%0,%1,%2,%3}, {%4,%5,%6,%7}, {%8,%9}, {%0,%1,%2,%3};"
        : "+f"(d[0]), "+f"(d[1]), "+f"(d[2]), "+f"(d[3])
        : "r"(a[0]), "r"(a[1]), "r"(a[2]), "r"(a[3]), "r"(b0), "r"(b1));
}

__device__ __forceinline__ uint32_t f2tf(float f) {
    uint32_t r;
    asm("cvt.rna.tf32.f32 %0, %1;" : "=r"(r) : "f"(f));
    return r;
}

// ==========================================================================
// Kernel G: Gram partials via tf32 mma — NO transpose; both operands via
// scalar LDS from the natural [n][d] staging tile (tf32-rounded in place).
// grid (NSPLIT=8, 32), 256 threads, 2 CTAs/SM.  K=256/CTA, 4 chunks of 64.
#define GRAM_SMEM_BYTES (2 * 33792)   // 67584
__global__ __launch_bounds__(256, 2) void gram_mma(const float* __restrict__ x) {
    extern __shared__ __align__(128) char sm[];
    uint32_t sb = smem_u32(sm);
    const int b = blockIdx.y, split = blockIdx.x;
    const int nbase = split * 256;
    const int tid = threadIdx.x, lane = tid & 31, wid = tid >> 5;
    const int m0 = (wid & 1) * 64, n0 = (wid >> 1) * 32;
    const float* xb = x + (size_t)b * NN * DD;

    float acc[4][4][4];
#pragma unroll
    for (int mi = 0; mi < 4; mi++)
#pragma unroll
        for (int nj = 0; nj < 4; nj++)
#pragma unroll
            for (int q = 0; q < 4; q++) acc[mi][nj][q] = 0.f;

#define GRAM_ISSUE(c)                                                          \
    do {                                                                       \
        int nc_ = nbase + (c) * 64;                                            \
        uint32_t stg_ = sb + ((c) & 1) * 33792;                                \
        for (int i = tid; i < 2048; i += 256) {                                \
            int row = i >> 5, seg = i & 31;                                    \
            CP_ASYNC16(stg_ + row * 528 + seg * 16,                            \
                       xb + (size_t)(nc_ + row) * DD + seg * 4);               \
        }                                                                      \
        CP_ASYNC_COMMIT();                                                     \
    } while (0)

    const int g = lane >> 2, t = lane & 3;

    GRAM_ISSUE(0);
    for (int c = 0; c < 4; c++) {
        if (c + 1 < 4) { GRAM_ISSUE(c + 1); CP_ASYNC_WAIT1(); }
        else           { CP_ASYNC_WAIT0(); }
        __syncthreads();
        float* fS = (float*)(sm + (c & 1) * 33792);
        // tf32-round staging in place
        for (int i = tid; i < 2048; i += 256) {
            int row = i >> 5, seg = i & 31;
            float4 v = *(float4*)(fS + row * 132 + seg * 4);
            v.x = __uint_as_float(f2tf(v.x));
            v.y = __uint_as_float(f2tf(v.y));
            v.z = __uint_as_float(f2tf(v.z));
            v.w = __uint_as_float(f2tf(v.w));
            *(float4*)(fS + row * 132 + seg * 4) = v;
        }
        __syncthreads();
        // MMA: A[m=d][k=n]=tile[k][m], B[n=d'][k=n]=tile[k][n]
#pragma unroll
        for (int ko = 0; ko < 64; ko += 8) {
            const float* r0 = fS + (ko + t) * 132;
            const float* r1 = fS + (ko + t + 4) * 132;
            uint32_t A[4][4];
#pragma unroll
            for (int mi = 0; mi < 4; mi++) {
                int m = m0 + mi * 16;
                A[mi][0] = __float_as_uint(r0[m + g]);
                A[mi][1] = __float_as_uint(r0[m + g + 8]);
                A[mi][2] = __float_as_uint(r1[m + g]);
                A[mi][3] = __float_as_uint(r1[m + g + 8]);
            }
            uint32_t B0[4], B1[4];
#pragma unroll
            for (int nj = 0; nj < 4; nj++) {
                int col = n0 + nj * 8 + g;
                B0[nj] = __float_as_uint(r0[col]);
                B1[nj] = __float_as_uint(r1[col]);
            }
#pragma unroll
            for (int mi = 0; mi < 4; mi++)
#pragma unroll
                for (int nj = 0; nj < 4; nj++)
                    mma_tf32(acc[mi][nj], A[mi], B0[nj], B1[nj]);
        }
        __syncthreads();
    }

    float* Sp = g_Spart + (size_t)(split * BB + b) * (DD * DD);
#pragma unroll
    for (int mi = 0; mi < 4; mi++)
#pragma unroll
        for (int nj = 0; nj < 4; nj++) {
            int r = m0 + mi * 16 + g, cc = n0 + nj * 8 + t * 2;
            *(float2*)&Sp[r * DD + cc] =
                make_float2(acc[mi][nj][0], acc[mi][nj][1]);
            *(float2*)&Sp[(r + 8) * DD + cc] =
                make_float2(acc[mi][nj][2], acc[mi][nj][3]);
        }
}

// ==========================================================================
// Kernel S: sum Spart -> tf32-rounded fp32 g_S.  grid (16, 32).  PDL wait.
__global__ __launch_bounds__(256) void sconv() {
    GRIDDEP_WAIT();
    const int b = blockIdx.y, ds = blockIdx.x;
    const size_t base = (size_t)b * DD * DD + ds * 8 * DD;
    const int i = threadIdx.x;

    float4 s = make_float4(0.f, 0.f, 0.f, 0.f);
#pragma unroll
    for (int p = 0; p < NSPLIT; p++) {
        float4 v = *(const float4*)(g_Spart + (size_t)p * BB * DD * DD +
                                    base + i * 4);
        s.x += v.x; s.y += v.y; s.z += v.z; s.w += v.w;
    }
    float4 o;
    o.x = __uint_as_float(f2tf(s.x));
    o.y = __uint_as_float(f2tf(s.y));
    o.z = __uint_as_float(f2tf(s.z));
    o.w = __uint_as_float(f2tf(s.w));
    *(float4*)(g_S + base + i * 4) = o;
}

// ==========================================================================
// Kernel M: all-tf32 single-pass mid.  grid (8, 32), 512 threads.  (R14)
#define MID_SMEM_BYTES 203776
__global__ __launch_bounds__(512, 1) void mid_mma(const float* __restrict__ Wk,
                                                  const float* __restrict__ Wq,
                                                  const float* __restrict__ Wv) {
    extern __shared__ __align__(128) char sm[];
    uint32_t sb = smem_u32(sm);
    const int h = blockIdx.x, b = blockIdx.y;
    const int tid = threadIdx.x, lane = tid & 31, wid = tid >> 5;

    const uint32_t oS = sb, oWv = sb + 67584, oT1 = sb + 135168;
    const uint32_t oWk = sb + 168960, oWq = sb;
    float* fWv = (float*)(sm + 67584);
    float* fT1 = (float*)(sm + 135168);
    float* fWk = (float*)(sm + 168960);
    float* fT2 = (float*)(sm + 168960);
    float* fWq = (float*)sm;

    // PRE-WAIT prologue: Wk + Wv (independent of sconv)
    {
        const float* wk = Wk + (size_t)h * KQ * DD;
        for (int i = tid; i < 2048; i += 512) {
            int row = i >> 5, seg = i & 31;
            CP_ASYNC16(oWk + row * 528 + seg * 16, wk + (size_t)row * DD + seg * 4);
        }
        const float* wv = Wv + (size_t)h * DD * DD;
        for (int i = tid; i < 4096; i += 512) {
            int row = i >> 5, seg = i & 31;
            CP_ASYNC16(oWv + row * 528 + seg * 16, wv + (size_t)row * DD + seg * 4);
        }
        CP_ASYNC_COMMIT();
    }

    GRIDDEP_WAIT();   // sconv's g_S now visible

    // group 1: S (pre-rounded)
    {
        const float* sp = g_S + (size_t)b * DD * DD;
        for (int i = tid; i < 4096; i += 512) {
            int row = i >> 5, seg = i & 31;
            CP_ASYNC16(oS + row * 528 + seg * 16, sp + (size_t)row * DD + seg * 4);
        }
        CP_ASYNC_COMMIT();
    }

    const int a_row = lane & 15, a_cg = lane >> 4;
    const int b_row = (lane & 7) + ((lane >> 4) << 3);
    const int b_cg = (lane >> 3) & 1;
    const int g = lane >> 2, t = lane & 3;

    CP_ASYNC_WAIT0();   // Wk, Wv, S all landed
    __syncthreads();
    for (int i = tid; i < 2048; i += 512) {
        int row = i >> 5, seg = i & 31;
        float4 v = *(float4*)(fWk + row * 132 + seg * 4);
        v.x = __uint_as_float(f2tf(v.x));
        v.y = __uint_as_float(f2tf(v.y));
        v.z = __uint_as_float(f2tf(v.z));
        v.w = __uint_as_float(f2tf(v.w));
        *(float4*)(fWk + row * 132 + seg * 4) = v;
    }
    for (int i = tid; i < 4096; i += 512) {
        int row = i >> 5, seg = i & 31;
        float4 v = *(float4*)(fWv + row * 132 + seg * 4);
        v.x = __uint_as_float(f2tf(v.x));
        v.y = __uint_as_float(f2tf(v.y));
        v.z = __uint_as_float(f2tf(v.z));
        v.w = __uint_as_float(f2tf(v.w));
        *(float4*)(fWv + row * 132 + seg * 4) = v;
    }
    __syncthreads();

    // Stage 1: T1[64,128] = Wk @ S  (S symmetric)
    const int m0s = (wid & 3) * 16, n0s = (wid >> 2) * 32;
    {
        float acc1[4][4];
#pragma unroll
        for (int nj = 0; nj < 4; nj++)
#pragma unroll
            for (int q = 0; q < 4; q++) acc1[nj][q] = 0.f;
#pragma unroll
        for (int ko = 0; ko < 128; ko += 8) {
            uint32_t A[4], B[2][4];
            ldsm4(A, oWk + (m0s + a_row) * 528 + (ko + 4 * a_cg) * 4);
#pragma unroll
            for (int njp = 0; njp < 2; njp++)
                ldsm4(B[njp], oS + (n0s + njp * 16 + b_row) * 528 +
                              (ko + 4 * b_cg) * 4);
#pragma unroll
            for (int nj = 0; nj < 4; nj++)
                mma_tf32(acc1[nj], A,
                         B[nj >> 1][(nj & 1) * 2], B[nj >> 1][(nj & 1) * 2 + 1]);
        }
        __syncthreads();
#pragma unroll
        for (int nj = 0; nj < 4; nj++) {
            int cc = n0s + nj * 8 + t * 2;
            *(float2*)(fT1 + (m0s + g) * 132 + cc) =
                make_float2(__uint_as_float(f2tf(acc1[nj][0])),
                            __uint_as_float(f2tf(acc1[nj][1])));
            *(float2*)(fT1 + (m0s + g + 8) * 132 + cc) =
                make_float2(__uint_as_float(f2tf(acc1[nj][2])),
                            __uint_as_float(f2tf(acc1[nj][3])));
        }
    }
    // Wq into old-S slot
    {
        const float* wq = Wq + (size_t)h * KQ * DD;
        for (int i = tid; i < 2048; i += 512) {
            int row = i >> 5, seg = i & 31;
            CP_ASYNC16(oWq + row * 544 + seg * 16, wq + (size_t)row * DD + seg * 4);
        }
        CP_ASYNC_COMMIT();
    }
    __syncthreads();    // T1 visible

    // Stage 2: T2[64,128] = T1 @ Wv^T
    {
        float acc2[4][4];
#pragma unroll
        for (int nj = 0; nj < 4; nj++)
#pragma unroll
            for (int q = 0; q < 4; q++) acc2[nj][q] = 0.f;
#pragma unroll
        for (int ko = 0; ko < 128; ko += 8) {
            uint32_t A[4], B[2][4];
            ldsm4(A, oT1 + (m0s + a_row) * 528 + (ko + 4 * a_cg) * 4);
#pragma unroll
            for (int njp = 0; njp < 2; njp++)
                ldsm4(B[njp], oWv + (n0s + njp * 16 + b_row) * 528 +
                              (ko + 4 * b_cg) * 4);
#pragma unroll
            for (int nj = 0; nj < 4; nj++)
                mma_tf32(acc2[nj], A,
                         B[nj >> 1][(nj & 1) * 2], B[nj >> 1][(nj & 1) * 2 + 1]);
        }
        __syncthreads();
#pragma unroll
        for (int nj = 0; nj < 4; nj++) {
            int cc = n0s + nj * 8 + t * 2;
            *(float2*)(fT2 + (m0s + g) * 136 + cc) =
                make_float2(__uint_as_float(f2tf(acc2[nj][0])),
                            __uint_as_float(f2tf(acc2[nj][1])));
            *(float2*)(fT2 + (m0s + g + 8) * 136 + cc) =
                make_float2(__uint_as_float(f2tf(acc2[nj][2])),
                            __uint_as_float(f2tf(acc2[nj][3])));
        }
    }
    CP_ASYNC_WAIT0();   // Wq landed
    __syncthreads();
    for (int i = tid; i < 2048; i += 512) {
        int row = i >> 5, seg = i & 31;
        float4 v = *(float4*)(fWq + row * 136 + seg * 4);
        v.x = __uint_as_float(f2tf(v.x));
        v.y = __uint_as_float(f2tf(v.y));
        v.z = __uint_as_float(f2tf(v.z));
        v.w = __uint_as_float(f2tf(v.w));
        *(float4*)(fWq + row * 136 + seg * 4) = v;
    }
    __syncthreads();

    // Stage 3: M[128,128] = Wq^T @ T2.  Scalar-LDS fragments.
    const int m0 = (wid & 3) * 32, n0 = (wid >> 2) * 32;
    float acc3[2][4][4];
#pragma unroll
    for (int mi = 0; mi < 2; mi++)
#pragma unroll
        for (int nj = 0; nj < 4; nj++)
#pragma unroll
            for (int q = 0; q < 4; q++) acc3[mi][nj][q] = 0.f;
#pragma unroll
    for (int ko = 0; ko < 64; ko += 8) {
        uint32_t A[2][4];
#pragma unroll
        for (int mi = 0; mi < 2; mi++) {
            int m = m0 + mi * 16;
            A[mi][0] = __float_as_uint(fWq[(ko + t) * 136 + m + g]);
            A[mi][1] = __float_as_uint(fWq[(ko + t) * 136 + m + g + 8]);
            A[mi][2] = __float_as_uint(fWq[(ko + t + 4) * 136 + m + g]);
            A[mi][3] = __float_as_uint(fWq[(ko + t + 4) * 136 + m + g + 8]);
        }
        uint32_t B0[4], B1[4];
#pragma unroll
        for (int nj = 0; nj < 4; nj++) {
            int col = n0 + nj * 8 + g;
            B0[nj] = __float_as_uint(fT2[(ko + t) * 136 + col]);
            B1[nj] = __float_as_uint(fT2[(ko + t + 4) * 136 + col]);
        }
#pragma unroll
        for (int mi = 0; mi < 2; mi++)
#pragma unroll
            for (int nj = 0; nj < 4; nj++)
                mma_tf32(acc3[mi][nj], A[mi], B0[nj], B1[nj]);
    }
    float* Mp = g_Mpart + (size_t)(h * BB + b) * DD * DD;
#pragma unroll
    for (int mi = 0; mi < 2; mi++)
#pragma unroll
        for (int nj = 0; nj < 4; nj++) {
            int r = m0 + mi * 16 + g, cc = n0 + nj * 8 + t * 2;
            *(float2*)&Mp[r * DD + cc] =
                make_float2(acc3[mi][nj][0], acc3[mi][nj][1]);
            *(float2*)&Mp[(r + 8) * DD + cc] =
                make_float2(acc3[mi][nj][2], acc3[mi][nj][3]);
        }
}

// ==========================================================================
// Kernel C: sum Mparts -> tf32-rounded fp32 g_M.  grid (16, 32).  PDL wait.
__global__ __launch_bounds__(256) void mconv() {
    GRIDDEP_WAIT();
    const int b = blockIdx.y, ds = blockIdx.x;
    const size_t base = (size_t)b * DD * DD + ds * 8 * DD;
    const int i = threadIdx.x;

    float4 s = make_float4(0.f, 0.f, 0.f, 0.f);
#pragma unroll
    for (int h = 0; h < HH; h++) {
        float4 v = *(const float4*)(g_Mpart + (size_t)h * BB * DD * DD +
                                    base + i * 4);
        s.x += v.x; s.y += v.y; s.z += v.z; s.w += v.w;
    }
    float4 o;
    o.x = __uint_as_float(f2tf(s.x));
    o.y = __uint_as_float(f2tf(s.y));
    o.z = __uint_as_float(f2tf(s.z));
    o.w = __uint_as_float(f2tf(s.w));
    *(float4*)(g_M + base + i * 4) = o;
}

// ==========================================================================
// Kernel O: out = x @ M via tf32 mma, 64-row tiles, 2 CTAs/SM.  (R14)
#define OUT_SMEM_BYTES (33792 + 69632)   // 103424
__global__ __launch_bounds__(256, 2) void out_mma(const float* __restrict__ x,
                                                  float* __restrict__ out) {
    extern __shared__ __align__(128) char sm[];
    uint32_t sb = smem_u32(sm);
    const int b = blockIdx.y, nblk = blockIdx.x * 64;
    const int tid = threadIdx.x, lane = tid & 31, wid = tid >> 5;
    const int m0 = (wid & 1) * 32, n0 = (wid >> 1) * 32;

    const uint32_t tA = sb;            // x tile (64 rows)
    const uint32_t tB = sb + 33792;    // M tile
    float* tBf = (float*)(sm + 33792);

    // PRE-WAIT: x tile (independent of mconv)
    const float* xb = x + ((size_t)b * NN + nblk) * DD;
    for (int i = tid; i < 2048; i += 256) {
        int row = i >> 5, seg = i & 31;
        CP_ASYNC16(tA + row * 528 + seg * 16, xb + (size_t)row * DD + seg * 4);
    }
    CP_ASYNC_COMMIT();

    GRIDDEP_WAIT();   // mconv's g_M now visible

    // group 1: M tile
    {
        const float* mb = g_M + (size_t)b * DD * DD;
        for (int i = tid; i < 4096; i += 256) {
            int row = i >> 5, seg = i & 31;
            CP_ASYNC16(tB + row * 544 + seg * 16, mb + (size_t)row * DD + seg * 4);
        }
    }
    CP_ASYNC_COMMIT();

    CP_ASYNC_WAIT1();
    __syncthreads();
    // tf32-round x in place (overlaps M load)
    {
        float* tAf = (float*)sm;
        for (int i = tid; i < 2048; i += 256) {
            int row = i >> 5, seg = i & 31;
            float4 v = *(float4*)(tAf + row * 132 + seg * 4);
            v.x = __uint_as_float(f2tf(v.x));
            v.y = __uint_as_float(f2tf(v.y));
            v.z = __uint_as_float(f2tf(v.z));
            v.w = __uint_as_float(f2tf(v.w));
            *(float4*)(tAf + row * 132 + seg * 4) = v;
        }
    }
    CP_ASYNC_WAIT0();
    __syncthreads();

    float acc[2][4][4];
#pragma unroll
    for (int mi = 0; mi < 2; mi++)
#pragma unroll
        for (int nj = 0; nj < 4; nj++)
#pragma unroll
            for (int q = 0; q < 4; q++) acc[mi][nj][q] = 0.f;

    const int a_row = lane & 15, a_cg = lane >> 4;
    const int g = lane >> 2, t = lane & 3;

#pragma unroll
    for (int ko = 0; ko < 128; ko += 8) {
        uint32_t A[2][4];
#pragma unroll
        for (int mi = 0; mi < 2; mi++)
            ldsm4(A[mi], tA + (m0 + mi * 16 + a_row) * 528 +
                         (ko + 4 * a_cg) * 4);
        uint32_t B0[4], B1[4];
#pragma unroll
        for (int nj = 0; nj < 4; nj++) {
            int col = n0 + nj * 8 + g;
            B0[nj] = __float_as_uint(tBf[(ko + t) * 136 + col]);
            B1[nj] = __float_as_uint(tBf[(ko + t + 4) * 136 + col]);
        }
#pragma unroll
        for (int mi = 0; mi < 2; mi++)
#pragma unroll
            for (int nj = 0; nj < 4; nj++)
                mma_tf32(acc[mi][nj], A[mi], B0[nj], B1[nj]);
    }

    float* ob = out + ((size_t)b * NN + nblk) * DD;
#pragma unroll
    for (int mi = 0; mi < 2; mi++)
#pragma unroll
        for (int nj = 0; nj < 4; nj++) {
            int r = m0 + mi * 16 + g, cc = n0 + nj * 8 + t * 2;
            *(float2*)&ob[r * DD + cc] =
                make_float2(acc[mi][nj][0], acc[mi][nj][1]);
            *(float2*)&ob[(r + 8) * DD + cc] =
                make_float2(acc[mi][nj][2], acc[mi][nj][3]);
        }
}

// ==========================================================================
extern "C" void kernel_launch(void* const* d_in, const int* in_sizes, int n_in,
                              void* d_out, int out_size) {
    const float* x  = (const float*)d_in[0];  // [32, 2048, 128]
    const float* Wk = (const float*)d_in[1];  // [8, 64, 128]
    const float* Wq = (const float*)d_in[2];  // [8, 64, 128]
    const float* Wv = (const float*)d_in[3];  // [8, 128, 128]
    float* out = (float*)d_out;               // [32, 2048, 128]

    cudaFuncSetAttribute(gram_mma, cudaFuncAttributeMaxDynamicSharedMemorySize,
                         GRAM_SMEM_BYTES);
    cudaFuncSetAttribute(mid_mma, cudaFuncAttributeMaxDynamicSharedMemorySize,
                         MID_SMEM_BYTES);
    cudaFuncSetAttribute(out_mma, cudaFuncAttributeMaxDynamicSharedMemorySize,
                         OUT_SMEM_BYTES);

    cudaLaunchAttribute pdl[1];
    pdl[0].id = cudaLaunchAttributeProgrammaticStreamSerialization;
    pdl[0].val.programmaticStreamSerializationAllowed = 1;

    gram_mma<<<dim3(NSPLIT, 32), 256, GRAM_SMEM_BYTES>>>(x);

    {   // sconv (PDL)
        cudaLaunchConfig_t cfg = {};
        cfg.gridDim = dim3(16, 32); cfg.blockDim = dim3(256);
        cfg.dynamicSmemBytes = 0; cfg.stream = 0;
        cfg.attrs = pdl; cfg.numAttrs = 1;
        cudaLaunchKernelEx(&cfg, sconv);
    }
    {   // mid (PDL)
        cudaLaunchConfig_t cfg = {};
        cfg.gridDim = dim3(HH, 32); cfg.blockDim = dim3(512);
        cfg.dynamicSmemBytes = MID_SMEM_BYTES; cfg.stream = 0;
        cfg.attrs = pdl; cfg.numAttrs = 1;
        cudaLaunchKernelEx(&cfg, mid_mma, Wk, Wq, Wv);
    }
    {   // mconv (PDL)
        cudaLaunchConfig_t cfg = {};
        cfg.gridDim = dim3(16, 32); cfg.blockDim = dim3(256);
        cfg.dynamicSmemBytes = 0; cfg.stream = 0;
        cfg.attrs = pdl; cfg.numAttrs = 1;
        cudaLaunchKernelEx(&cfg, mconv);
    }
    {   // out (PDL)
        cudaLaunchConfig_t cfg = {};
        cfg.gridDim = dim3(32, 32); cfg.blockDim = dim3(256);
        cfg.dynamicSmemBytes = OUT_SMEM_BYTES; cfg.stream = 0;
        cfg.attrs = pdl; cfg.numAttrs = 1;
        cudaLaunchKernelEx(&cfg, out_mma, x, out);
    }
}

// round 16
// speedup vs baseline: 1.0883x; 1.0883x over previous
#include <cuda_runtime.h>
#include <cuda_bf16.h>
#include <cstdint>

// Problem constants
#define BB 32
#define NN 2048
#define DD 128
#define HH 8
#define KQ 64
#define NSPLIT 8

// ------------------------------------------------------------------ scratch
__device__ float g_Spart[NSPLIT * BB * DD * DD];     // gram partials (fp32)
__device__ float g_S[BB * DD * DD];                  // summed S, tf32-rounded
__device__ float g_Mpart[HH * BB * DD * DD];         // M partials per head
__device__ float g_M[BB * DD * DD];                  // summed M, tf32-rounded

// ------------------------------------------------------------------ helpers
__device__ __forceinline__ uint32_t smem_u32(const void* p) {
    uint32_t a;
    asm("{ .reg .u64 t; cvta.to.shared.u64 t, %1; cvt.u32.u64 %0, t; }"
        : "=r"(a) : "l"(p));
    return a;
}

#define GRIDDEP_WAIT() asm volatile("griddepcontrol.wait;" ::: "memory")

#define CP_ASYNC16(saddr, gptr) \
    asm volatile("cp.async.cg.shared.global [%0], [%1], 16;" \
                 :: "r"(saddr), "l"(gptr) : "memory")
#define CP_ASYNC_COMMIT() asm volatile("cp.async.commit_group;" ::: "memory")
#define CP_ASYNC_WAIT0()  asm volatile("cp.async.wait_group 0;" ::: "memory")
#define CP_ASYNC_WAIT1()  asm volatile("cp.async.wait_group 1;" ::: "memory")

__device__ __forceinline__ void ldsm4(uint32_t* r, uint32_t addr) {
    asm volatile("ldmatrix.sync.aligned.m8n8.x4.shared.b16 {%0,%1,%2,%3}, [%4];"
                 : "=r"(r[0]), "=r"(r[1]), "=r"(r[2]), "=r"(r[3]) : "r"(addr));
}

__device__ __forceinline__ void mma_tf32(float* d, const uint32_t* a,
                                         uint32_t b0, uint32_t b1) {
    asm volatile(
        "mma.sync.aligned.m16n8k8.row.col.f32.tf32.tf32.f32 "
        "{%0,%1,%2,%3}, {%4,%5,%6,%7}, {%8,%9}, {%0,%1,%2,%3};"
        : "+f"(d[0]), "+f"(d[1]), "+f"(d[2]), "+f"(d[3])
        : "r"(a[0]), "r"(a[1]), "r"(a[2]), "r"(a[3]), "r"(b0), "r"(b1));
}

__device__ __forceinline__ uint32_t f2tf(float f) {
    uint32_t r;
    asm("cvt.rna.tf32.f32 %0, %1;" : "=r"(r) : "f"(f));
    return r;
}

// ==========================================================================
// Kernel G: Gram partials via tf32 mma.  2 CTAs/SM.  (R14 verbatim)
#define GRAM_SMEM_BYTES (2 * 33792 + 34816)   // 102400
__global__ __launch_bounds__(256, 2) void gram_mma(const float* __restrict__ x) {
    extern __shared__ __align__(128) char sm[];
    uint32_t sb = smem_u32(sm);
    const int b = blockIdx.y, split = blockIdx.x;
    const int nbase = split * 256;
    const int tid = threadIdx.x, lane = tid & 31, wid = tid >> 5;
    const int m0 = (wid & 1) * 64, n0 = (wid >> 1) * 32;
    const float* xb = x + (size_t)b * NN * DD;

    const uint32_t Xp = sb + 67584;

    float acc[4][4][4];
#pragma unroll
    for (int mi = 0; mi < 4; mi++)
#pragma unroll
        for (int nj = 0; nj < 4; nj++)
#pragma unroll
            for (int q = 0; q < 4; q++) acc[mi][nj][q] = 0.f;

#define GRAM_ISSUE(c)                                                          \
    do {                                                                       \
        int nc_ = nbase + (c) * 64;                                            \
        uint32_t stg_ = sb + ((c) & 1) * 33792;                                \
        for (int i = tid; i < 2048; i += 256) {                                \
            int row = i >> 5, seg = i & 31;                                    \
            CP_ASYNC16(stg_ + row * 528 + seg * 16,                            \
                       xb + (size_t)(nc_ + row) * DD + seg * 4);               \
        }                                                                      \
        CP_ASYNC_COMMIT();                                                     \
    } while (0)

    const int a_row = lane & 15, a_cg = lane >> 4;
    const int b_row = (lane & 7) + ((lane >> 4) << 3);
    const int b_cg = (lane >> 3) & 1;

    GRAM_ISSUE(0);
    for (int c = 0; c < 4; c++) {
        if (c + 1 < 4) { GRAM_ISSUE(c + 1); CP_ASYNC_WAIT1(); }
        else           { CP_ASYNC_WAIT0(); }
        __syncthreads();
        {
            const float* SGp = (const float*)(sm + (c & 1) * 33792);
            float* XpF = (float*)(sm + 67584);
#pragma unroll
            for (int half = 0; half < 2; half++) {
                int row = half * 32 + lane;
#pragma unroll
                for (int s = 0; s < 4; s++) {
                    int seg = wid * 4 + s;
                    float4 v = *(const float4*)(SGp + row * 132 + seg * 4);
                    XpF[(seg * 4 + 0) * 68 + row] = __uint_as_float(f2tf(v.x));
                    XpF[(seg * 4 + 1) * 68 + row] = __uint_as_float(f2tf(v.y));
                    XpF[(seg * 4 + 2) * 68 + row] = __uint_as_float(f2tf(v.z));
                    XpF[(seg * 4 + 3) * 68 + row] = __uint_as_float(f2tf(v.w));
                }
            }
        }
        __syncthreads();
#pragma unroll
        for (int ko = 0; ko < 64; ko += 8) {
            uint32_t A[4][4], B[2][4];
#pragma unroll
            for (int mi = 0; mi < 4; mi++)
                ldsm4(A[mi], Xp + (m0 + mi * 16 + a_row) * 272 +
                             (ko + 4 * a_cg) * 4);
#pragma unroll
            for (int njp = 0; njp < 2; njp++)
                ldsm4(B[njp], Xp + (n0 + njp * 16 + b_row) * 272 +
                              (ko + 4 * b_cg) * 4);
#pragma unroll
            for (int mi = 0; mi < 4; mi++)
#pragma unroll
                for (int nj = 0; nj < 4; nj++)
                    mma_tf32(acc[mi][nj], A[mi],
                             B[nj >> 1][(nj & 1) * 2], B[nj >> 1][(nj & 1) * 2 + 1]);
        }
        __syncthreads();
    }

    float* Sp = g_Spart + (size_t)(split * BB + b) * (DD * DD);
    const int g = lane >> 2, t = lane & 3;
#pragma unroll
    for (int mi = 0; mi < 4; mi++)
#pragma unroll
        for (int nj = 0; nj < 4; nj++) {
            int r = m0 + mi * 16 + g, cc = n0 + nj * 8 + t * 2;
            *(float2*)&Sp[r * DD + cc] =
                make_float2(acc[mi][nj][0], acc[mi][nj][1]);
            *(float2*)&Sp[(r + 8) * DD + cc] =
                make_float2(acc[mi][nj][2], acc[mi][nj][3]);
        }
}

// ==========================================================================
// Kernel S: sum Spart -> tf32-rounded fp32 g_S.  grid (16, 32).  PDL wait.
__global__ __launch_bounds__(256) void sconv() {
    GRIDDEP_WAIT();
    const int b = blockIdx.y, ds = blockIdx.x;
    const size_t base = (size_t)b * DD * DD + ds * 8 * DD;
    const int i = threadIdx.x;

    float4 s = make_float4(0.f, 0.f, 0.f, 0.f);
#pragma unroll
    for (int p = 0; p < NSPLIT; p++) {
        float4 v = *(const float4*)(g_Spart + (size_t)p * BB * DD * DD +
                                    base + i * 4);
        s.x += v.x; s.y += v.y; s.z += v.z; s.w += v.w;
    }
    float4 o;
    o.x = __uint_as_float(f2tf(s.x));
    o.y = __uint_as_float(f2tf(s.y));
    o.z = __uint_as_float(f2tf(s.z));
    o.w = __uint_as_float(f2tf(s.w));
    *(float4*)(g_S + base + i * 4) = o;
}

// ==========================================================================
// Kernel M: all-tf32 single-pass mid.  grid (8, 32), 512 threads.  (R14)
#define MID_SMEM_BYTES 203776
__global__ __launch_bounds__(512, 1) void mid_mma(const float* __restrict__ Wk,
                                                  const float* __restrict__ Wq,
                                                  const float* __restrict__ Wv) {
    extern __shared__ __align__(128) char sm[];
    uint32_t sb = smem_u32(sm);
    const int h = blockIdx.x, b = blockIdx.y;
    const int tid = threadIdx.x, lane = tid & 31, wid = tid >> 5;

    const uint32_t oS = sb, oWv = sb + 67584, oT1 = sb + 135168;
    const uint32_t oWk = sb + 168960, oWq = sb;
    float* fWv = (float*)(sm + 67584);
    float* fT1 = (float*)(sm + 135168);
    float* fWk = (float*)(sm + 168960);
    float* fT2 = (float*)(sm + 168960);
    float* fWq = (float*)sm;

    // PRE-WAIT prologue: Wk + Wv (independent of sconv)
    {
        const float* wk = Wk + (size_t)h * KQ * DD;
        for (int i = tid; i < 2048; i += 512) {
            int row = i >> 5, seg = i & 31;
            CP_ASYNC16(oWk + row * 528 + seg * 16, wk + (size_t)row * DD + seg * 4);
        }
        const float* wv = Wv + (size_t)h * DD * DD;
        for (int i = tid; i < 4096; i += 512) {
            int row = i >> 5, seg = i & 31;
            CP_ASYNC16(oWv + row * 528 + seg * 16, wv + (size_t)row * DD + seg * 4);
        }
        CP_ASYNC_COMMIT();
    }

    GRIDDEP_WAIT();   // sconv's g_S now visible

    // group 1: S (pre-rounded)
    {
        const float* sp = g_S + (size_t)b * DD * DD;
        for (int i = tid; i < 4096; i += 512) {
            int row = i >> 5, seg = i & 31;
            CP_ASYNC16(oS + row * 528 + seg * 16, sp + (size_t)row * DD + seg * 4);
        }
        CP_ASYNC_COMMIT();
    }

    const int a_row = lane & 15, a_cg = lane >> 4;
    const int b_row = (lane & 7) + ((lane >> 4) << 3);
    const int b_cg = (lane >> 3) & 1;
    const int g = lane >> 2, t = lane & 3;

    CP_ASYNC_WAIT0();   // Wk, Wv, S all landed
    __syncthreads();
    for (int i = tid; i < 2048; i += 512) {
        int row = i >> 5, seg = i & 31;
        float4 v = *(float4*)(fWk + row * 132 + seg * 4);
        v.x = __uint_as_float(f2tf(v.x));
        v.y = __uint_as_float(f2tf(v.y));
        v.z = __uint_as_float(f2tf(v.z));
        v.w = __uint_as_float(f2tf(v.w));
        *(float4*)(fWk + row * 132 + seg * 4) = v;
    }
    for (int i = tid; i < 4096; i += 512) {
        int row = i >> 5, seg = i & 31;
        float4 v = *(float4*)(fWv + row * 132 + seg * 4);
        v.x = __uint_as_float(f2tf(v.x));
        v.y = __uint_as_float(f2tf(v.y));
        v.z = __uint_as_float(f2tf(v.z));
        v.w = __uint_as_float(f2tf(v.w));
        *(float4*)(fWv + row * 132 + seg * 4) = v;
    }
    __syncthreads();

    // Stage 1: T1[64,128] = Wk @ S  (S symmetric)
    const int m0s = (wid & 3) * 16, n0s = (wid >> 2) * 32;
    {
        float acc1[4][4];
#pragma unroll
        for (int nj = 0; nj < 4; nj++)
#pragma unroll
            for (int q = 0; q < 4; q++) acc1[nj][q] = 0.f;
#pragma unroll
        for (int ko = 0; ko < 128; ko += 8) {
            uint32_t A[4], B[2][4];
            ldsm4(A, oWk + (m0s + a_row) * 528 + (ko + 4 * a_cg) * 4);
#pragma unroll
            for (int njp = 0; njp < 2; njp++)
                ldsm4(B[njp], oS + (n0s + njp * 16 + b_row) * 528 +
                              (ko + 4 * b_cg) * 4);
#pragma unroll
            for (int nj = 0; nj < 4; nj++)
                mma_tf32(acc1[nj], A,
                         B[nj >> 1][(nj & 1) * 2], B[nj >> 1][(nj & 1) * 2 + 1]);
        }
        __syncthreads();
#pragma unroll
        for (int nj = 0; nj < 4; nj++) {
            int cc = n0s + nj * 8 + t * 2;
            *(float2*)(fT1 + (m0s + g) * 132 + cc) =
                make_float2(__uint_as_float(f2tf(acc1[nj][0])),
                            __uint_as_float(f2tf(acc1[nj][1])));
            *(float2*)(fT1 + (m0s + g + 8) * 132 + cc) =
                make_float2(__uint_as_float(f2tf(acc1[nj][2])),
                            __uint_as_float(f2tf(acc1[nj][3])));
        }
    }
    // Wq into old-S slot
    {
        const float* wq = Wq + (size_t)h * KQ * DD;
        for (int i = tid; i < 2048; i += 512) {
            int row = i >> 5, seg = i & 31;
            CP_ASYNC16(oWq + row * 544 + seg * 16, wq + (size_t)row * DD + seg * 4);
        }
        CP_ASYNC_COMMIT();
    }
    __syncthreads();    // T1 visible

    // Stage 2: T2[64,128] = T1 @ Wv^T
    {
        float acc2[4][4];
#pragma unroll
        for (int nj = 0; nj < 4; nj++)
#pragma unroll
            for (int q = 0; q < 4; q++) acc2[nj][q] = 0.f;
#pragma unroll
        for (int ko = 0; ko < 128; ko += 8) {
            uint32_t A[4], B[2][4];
            ldsm4(A, oT1 + (m0s + a_row) * 528 + (ko + 4 * a_cg) * 4);
#pragma unroll
            for (int njp = 0; njp < 2; njp++)
                ldsm4(B[njp], oWv + (n0s + njp * 16 + b_row) * 528 +
                              (ko + 4 * b_cg) * 4);
#pragma unroll
            for (int nj = 0; nj < 4; nj++)
                mma_tf32(acc2[nj], A,
                         B[nj >> 1][(nj & 1) * 2], B[nj >> 1][(nj & 1) * 2 + 1]);
        }
        __syncthreads();
#pragma unroll
        for (int nj = 0; nj < 4; nj++) {
            int cc = n0s + nj * 8 + t * 2;
            *(float2*)(fT2 + (m0s + g) * 136 + cc) =
                make_float2(__uint_as_float(f2tf(acc2[nj][0])),
                            __uint_as_float(f2tf(acc2[nj][1])));
            *(float2*)(fT2 + (m0s + g + 8) * 136 + cc) =
                make_float2(__uint_as_float(f2tf(acc2[nj][2])),
                            __uint_as_float(f2tf(acc2[nj][3])));
        }
    }
    CP_ASYNC_WAIT0();   // Wq landed
    __syncthreads();
    for (int i = tid; i < 2048; i += 512) {
        int row = i >> 5, seg = i & 31;
        float4 v = *(float4*)(fWq + row * 136 + seg * 4);
        v.x = __uint_as_float(f2tf(v.x));
        v.y = __uint_as_float(f2tf(v.y));
        v.z = __uint_as_float(f2tf(v.z));
        v.w = __uint_as_float(f2tf(v.w));
        *(float4*)(fWq + row * 136 + seg * 4) = v;
    }
    __syncthreads();

    // Stage 3: M[128,128] = Wq^T @ T2.  Scalar-LDS fragments.
    const int m0 = (wid & 3) * 32, n0 = (wid >> 2) * 32;
    float acc3[2][4][4];
#pragma unroll
    for (int mi = 0; mi < 2; mi++)
#pragma unroll
        for (int nj = 0; nj < 4; nj++)
#pragma unroll
            for (int q = 0; q < 4; q++) acc3[mi][nj][q] = 0.f;
#pragma unroll
    for (int ko = 0; ko < 64; ko += 8) {
        uint32_t A[2][4];
#pragma unroll
        for (int mi = 0; mi < 2; mi++) {
            int m = m0 + mi * 16;
            A[mi][0] = __float_as_uint(fWq[(ko + t) * 136 + m + g]);
            A[mi][1] = __float_as_uint(fWq[(ko + t) * 136 + m + g + 8]);
            A[mi][2] = __float_as_uint(fWq[(ko + t + 4) * 136 + m + g]);
            A[mi][3] = __float_as_uint(fWq[(ko + t + 4) * 136 + m + g + 8]);
        }
        uint32_t B0[4], B1[4];
#pragma unroll
        for (int nj = 0; nj < 4; nj++) {
            int col = n0 + nj * 8 + g;
            B0[nj] = __float_as_uint(fT2[(ko + t) * 136 + col]);
            B1[nj] = __float_as_uint(fT2[(ko + t + 4) * 136 + col]);
        }
#pragma unroll
        for (int mi = 0; mi < 2; mi++)
#pragma unroll
            for (int nj = 0; nj < 4; nj++)
                mma_tf32(acc3[mi][nj], A[mi], B0[nj], B1[nj]);
    }
    float* Mp = g_Mpart + (size_t)(h * BB + b) * DD * DD;
#pragma unroll
    for (int mi = 0; mi < 2; mi++)
#pragma unroll
        for (int nj = 0; nj < 4; nj++) {
            int r = m0 + mi * 16 + g, cc = n0 + nj * 8 + t * 2;
            *(float2*)&Mp[r * DD + cc] =
                make_float2(acc3[mi][nj][0], acc3[mi][nj][1]);
            *(float2*)&Mp[(r + 8) * DD + cc] =
                make_float2(acc3[mi][nj][2], acc3[mi][nj][3]);
        }
}

// ==========================================================================
// Kernel C: sum Mparts -> tf32-rounded fp32 g_M.  grid (16, 32).  PDL wait.
__global__ __launch_bounds__(256) void mconv() {
    GRIDDEP_WAIT();
    const int b = blockIdx.y, ds = blockIdx.x;
    const size_t base = (size_t)b * DD * DD + ds * 8 * DD;
    const int i = threadIdx.x;

    float4 s = make_float4(0.f, 0.f, 0.f, 0.f);
#pragma unroll
    for (int h = 0; h < HH; h++) {
        float4 v = *(const float4*)(g_Mpart + (size_t)h * BB * DD * DD +
                                    base + i * 4);
        s.x += v.x; s.y += v.y; s.z += v.z; s.w += v.w;
    }
    float4 o;
    o.x = __uint_as_float(f2tf(s.x));
    o.y = __uint_as_float(f2tf(s.y));
    o.z = __uint_as_float(f2tf(s.z));
    o.w = __uint_as_float(f2tf(s.w));
    *(float4*)(g_M + base + i * 4) = o;
}

// ==========================================================================
// Kernel O: out = x @ M via tf32 mma, 64-row tiles, 2 CTAs/SM.  (R14)
#define OUT_SMEM_BYTES (33792 + 69632)   // 103424
__global__ __launch_bounds__(256, 2) void out_mma(const float* __restrict__ x,
                                                  float* __restrict__ out) {
    extern __shared__ __align__(128) char sm[];
    uint32_t sb = smem_u32(sm);
    const int b = blockIdx.y, nblk = blockIdx.x * 64;
    const int tid = threadIdx.x, lane = tid & 31, wid = tid >> 5;
    const int m0 = (wid & 1) * 32, n0 = (wid >> 1) * 32;

    const uint32_t tA = sb;            // x tile (64 rows)
    const uint32_t tB = sb + 33792;    // M tile
    float* tBf = (float*)(sm + 33792);

    // PRE-WAIT: x tile (independent of mconv)
    const float* xb = x + ((size_t)b * NN + nblk) * DD;
    for (int i = tid; i < 2048; i += 256) {
        int row = i >> 5, seg = i & 31;
        CP_ASYNC16(tA + row * 528 + seg * 16, xb + (size_t)row * DD + seg * 4);
    }
    CP_ASYNC_COMMIT();

    GRIDDEP_WAIT();   // mconv's g_M now visible

    // group 1: M tile
    {
        const float* mb = g_M + (size_t)b * DD * DD;
        for (int i = tid; i < 4096; i += 256) {
            int row = i >> 5, seg = i & 31;
            CP_ASYNC16(tB + row * 544 + seg * 16, mb + (size_t)row * DD + seg * 4);
        }
    }
    CP_ASYNC_COMMIT();

    CP_ASYNC_WAIT1();
    __syncthreads();
    // tf32-round x in place (overlaps M load)
    {
        float* tAf = (float*)sm;
        for (int i = tid; i < 2048; i += 256) {
            int row = i >> 5, seg = i & 31;
            float4 v = *(float4*)(tAf + row * 132 + seg * 4);
            v.x = __uint_as_float(f2tf(v.x));
            v.y = __uint_as_float(f2tf(v.y));
            v.z = __uint_as_float(f2tf(v.z));
            v.w = __uint_as_float(f2tf(v.w));
            *(float4*)(tAf + row * 132 + seg * 4) = v;
        }
    }
    CP_ASYNC_WAIT0();
    __syncthreads();

    float acc[2][4][4];
#pragma unroll
    for (int mi = 0; mi < 2; mi++)
#pragma unroll
        for (int nj = 0; nj < 4; nj++)
#pragma unroll
            for (int q = 0; q < 4; q++) acc[mi][nj][q] = 0.f;

    const int a_row = lane & 15, a_cg = lane >> 4;
    const int g = lane >> 2, t = lane & 3;

#pragma unroll
    for (int ko = 0; ko < 128; ko += 8) {
        uint32_t A[2][4];
#pragma unroll
        for (int mi = 0; mi < 2; mi++)
            ldsm4(A[mi], tA + (m0 + mi * 16 + a_row) * 528 +
                         (ko + 4 * a_cg) * 4);
        uint32_t B0[4], B1[4];
#pragma unroll
        for (int nj = 0; nj < 4; nj++) {
            int col = n0 + nj * 8 + g;
            B0[nj] = __float_as_uint(tBf[(ko + t) * 136 + col]);
            B1[nj] = __float_as_uint(tBf[(ko + t + 4) * 136 + col]);
        }
#pragma unroll
        for (int mi = 0; mi < 2; mi++)
#pragma unroll
            for (int nj = 0; nj < 4; nj++)
                mma_tf32(acc[mi][nj], A[mi], B0[nj], B1[nj]);
    }

    float* ob = out + ((size_t)b * NN + nblk) * DD;
#pragma unroll
    for (int mi = 0; mi < 2; mi++)
#pragma unroll
        for (int nj = 0; nj < 4; nj++) {
            int r = m0 + mi * 16 + g, cc = n0 + nj * 8 + t * 2;
            *(float2*)&ob[r * DD + cc] =
                make_float2(acc[mi][nj][0], acc[mi][nj][1]);
            *(float2*)&ob[(r + 8) * DD + cc] =
                make_float2(acc[mi][nj][2], acc[mi][nj][3]);
        }
}

// ==========================================================================
extern "C" void kernel_launch(void* const* d_in, const int* in_sizes, int n_in,
                              void* d_out, int out_size) {
    const float* x  = (const float*)d_in[0];  // [32, 2048, 128]
    const float* Wk = (const float*)d_in[1];  // [8, 64, 128]
    const float* Wq = (const float*)d_in[2];  // [8, 64, 128]
    const float* Wv = (const float*)d_in[3];  // [8, 128, 128]
    float* out = (float*)d_out;               // [32, 2048, 128]

    cudaFuncSetAttribute(gram_mma, cudaFuncAttributeMaxDynamicSharedMemorySize,
                         GRAM_SMEM_BYTES);
    cudaFuncSetAttribute(mid_mma, cudaFuncAttributeMaxDynamicSharedMemorySize,
                         MID_SMEM_BYTES);
    cudaFuncSetAttribute(out_mma, cudaFuncAttributeMaxDynamicSharedMemorySize,
                         OUT_SMEM_BYTES);

    cudaLaunchAttribute pdl[1];
    pdl[0].id = cudaLaunchAttributeProgrammaticStreamSerialization;
    pdl[0].val.programmaticStreamSerializationAllowed = 1;

    gram_mma<<<dim3(NSPLIT, 32), 256, GRAM_SMEM_BYTES>>>(x);

    {   // sconv (PDL)
        cudaLaunchConfig_t cfg = {};
        cfg.gridDim = dim3(16, 32); cfg.blockDim = dim3(256);
        cfg.dynamicSmemBytes = 0; cfg.stream = 0;
        cfg.attrs = pdl; cfg.numAttrs = 1;
        cudaLaunchKernelEx(&cfg, sconv);
    }
    {   // mid (PDL)
        cudaLaunchConfig_t cfg = {};
        cfg.gridDim = dim3(HH, 32); cfg.blockDim = dim3(512);
        cfg.dynamicSmemBytes = MID_SMEM_BYTES; cfg.stream = 0;
        cfg.attrs = pdl; cfg.numAttrs = 1;
        cudaLaunchKernelEx(&cfg, mid_mma, Wk, Wq, Wv);
    }
    {   // mconv (PDL)
        cudaLaunchConfig_t cfg = {};
        cfg.gridDim = dim3(16, 32); cfg.blockDim = dim3(256);
        cfg.dynamicSmemBytes = 0; cfg.stream = 0;
        cfg.attrs = pdl; cfg.numAttrs = 1;
        cudaLaunchKernelEx(&cfg, mconv);
    }
    {   // out (PDL)
        cudaLaunchConfig_t cfg = {};
        cfg.gridDim = dim3(32, 32); cfg.blockDim = dim3(256);
        cfg.dynamicSmemBytes = OUT_SMEM_BYTES; cfg.stream = 0;
        cfg.attrs = pdl; cfg.numAttrs = 1;
        cudaLaunchKernelEx(&cfg, out_mma, x, out);
    }
}

// round 17
// speedup vs baseline: 1.0888x; 1.0005x over previous
#include <cuda_runtime.h>
#include <cuda_bf16.h>
#include <cstdint>

// Problem constants
#define BB 32
#define NN 2048
#define DD 128
#define HH 8
#define KQ 64
#define NSPLIT 8

// ------------------------------------------------------------------ scratch
__device__ float g_Spart[NSPLIT * BB * DD * DD];     // gram partials (fp32)
__device__ float g_S[BB * DD * DD];                  // summed S, tf32-rounded
__device__ float g_Mpart[HH * BB * DD * DD];         // M partials per head
__device__ float g_M[BB * DD * DD];                  // summed M, tf32-rounded

// ------------------------------------------------------------------ helpers
__device__ __forceinline__ uint32_t smem_u32(const void* p) {
    uint32_t a;
    asm("{ .reg .u64 t; cvta.to.shared.u64 t, %1; cvt.u32.u64 %0, t; }"
        : "=r"(a) : "l"(p));
    return a;
}

#define GRIDDEP_WAIT() asm volatile("griddepcontrol.wait;" ::: "memory")

#define CP_ASYNC16(saddr, gptr) \
    asm volatile("cp.async.cg.shared.global [%0], [%1], 16;" \
                 :: "r"(saddr), "l"(gptr) : "memory")
#define CP_ASYNC_COMMIT() asm volatile("cp.async.commit_group;" ::: "memory")
#define CP_ASYNC_WAIT0()  asm volatile("cp.async.wait_group 0;" ::: "memory")
#define CP_ASYNC_WAIT1()  asm volatile("cp.async.wait_group 1;" ::: "memory")

__device__ __forceinline__ void ldsm4(uint32_t* r, uint32_t addr) {
    asm volatile("ldmatrix.sync.aligned.m8n8.x4.shared.b16 {%0,%1,%2,%3}, [%4];"
                 : "=r"(r[0]), "=r"(r[1]), "=r"(r[2]), "=r"(r[3]) : "r"(addr));
}

__device__ __forceinline__ void mma_tf32(float* d, const uint32_t* a,
                                         uint32_t b0, uint32_t b1) {
    asm volatile(
        "mma.sync.aligned.m16n8k8.row.col.f32.tf32.tf32.f32 "
        "{%0,%1,%2,%3}, {%4,%5,%6,%7}, {%8,%9}, {%0,%1,%2,%3};"
        : "+f"(d[0]), "+f"(d[1]), "+f"(d[2]), "+f"(d[3])
        : "r"(a[0]), "r"(a[1]), "r"(a[2]), "r"(a[3]), "r"(b0), "r"(b1));
}

__device__ __forceinline__ uint32_t f2tf(float f) {
    uint32_t r;
    asm("cvt.rna.tf32.f32 %0, %1;" : "=r"(r) : "f"(f));
    return r;
}

// ==========================================================================
// Kernel G: Gram partials via tf32 mma.  2 CTAs/SM.  (R16 verbatim; now PDL,
// no internal wait — no data dependency on the previous replay's out_mma)
#define GRAM_SMEM_BYTES (2 * 33792 + 34816)   // 102400
__global__ __launch_bounds__(256, 2) void gram_mma(const float* __restrict__ x) {
    extern __shared__ __align__(128) char sm[];
    uint32_t sb = smem_u32(sm);
    const int b = blockIdx.y, split = blockIdx.x;
    const int nbase = split * 256;
    const int tid = threadIdx.x, lane = tid & 31, wid = tid >> 5;
    const int m0 = (wid & 1) * 64, n0 = (wid >> 1) * 32;
    const float* xb = x + (size_t)b * NN * DD;

    const uint32_t Xp = sb + 67584;

    float acc[4][4][4];
#pragma unroll
    for (int mi = 0; mi < 4; mi++)
#pragma unroll
        for (int nj = 0; nj < 4; nj++)
#pragma unroll
            for (int q = 0; q < 4; q++) acc[mi][nj][q] = 0.f;

#define GRAM_ISSUE(c)                                                          \
    do {                                                                       \
        int nc_ = nbase + (c) * 64;                                            \
        uint32_t stg_ = sb + ((c) & 1) * 33792;                                \
        for (int i = tid; i < 2048; i += 256) {                                \
            int row = i >> 5, seg = i & 31;                                    \
            CP_ASYNC16(stg_ + row * 528 + seg * 16,                            \
                       xb + (size_t)(nc_ + row) * DD + seg * 4);               \
        }                                                                      \
        CP_ASYNC_COMMIT();                                                     \
    } while (0)

    const int a_row = lane & 15, a_cg = lane >> 4;
    const int b_row = (lane & 7) + ((lane >> 4) << 3);
    const int b_cg = (lane >> 3) & 1;

    GRAM_ISSUE(0);
    for (int c = 0; c < 4; c++) {
        if (c + 1 < 4) { GRAM_ISSUE(c + 1); CP_ASYNC_WAIT1(); }
        else           { CP_ASYNC_WAIT0(); }
        __syncthreads();
        {
            const float* SGp = (const float*)(sm + (c & 1) * 33792);
            float* XpF = (float*)(sm + 67584);
#pragma unroll
            for (int half = 0; half < 2; half++) {
                int row = half * 32 + lane;
#pragma unroll
                for (int s = 0; s < 4; s++) {
                    int seg = wid * 4 + s;
                    float4 v = *(const float4*)(SGp + row * 132 + seg * 4);
                    XpF[(seg * 4 + 0) * 68 + row] = __uint_as_float(f2tf(v.x));
                    XpF[(seg * 4 + 1) * 68 + row] = __uint_as_float(f2tf(v.y));
                    XpF[(seg * 4 + 2) * 68 + row] = __uint_as_float(f2tf(v.z));
                    XpF[(seg * 4 + 3) * 68 + row] = __uint_as_float(f2tf(v.w));
                }
            }
        }
        __syncthreads();
#pragma unroll
        for (int ko = 0; ko < 64; ko += 8) {
            uint32_t A[4][4], B[2][4];
#pragma unroll
            for (int mi = 0; mi < 4; mi++)
                ldsm4(A[mi], Xp + (m0 + mi * 16 + a_row) * 272 +
                             (ko + 4 * a_cg) * 4);
#pragma unroll
            for (int njp = 0; njp < 2; njp++)
                ldsm4(B[njp], Xp + (n0 + njp * 16 + b_row) * 272 +
                              (ko + 4 * b_cg) * 4);
#pragma unroll
            for (int mi = 0; mi < 4; mi++)
#pragma unroll
                for (int nj = 0; nj < 4; nj++)
                    mma_tf32(acc[mi][nj], A[mi],
                             B[nj >> 1][(nj & 1) * 2], B[nj >> 1][(nj & 1) * 2 + 1]);
        }
        __syncthreads();
    }

    float* Sp = g_Spart + (size_t)(split * BB + b) * (DD * DD);
    const int g = lane >> 2, t = lane & 3;
#pragma unroll
    for (int mi = 0; mi < 4; mi++)
#pragma unroll
        for (int nj = 0; nj < 4; nj++) {
            int r = m0 + mi * 16 + g, cc = n0 + nj * 8 + t * 2;
            *(float2*)&Sp[r * DD + cc] =
                make_float2(acc[mi][nj][0], acc[mi][nj][1]);
            *(float2*)&Sp[(r + 8) * DD + cc] =
                make_float2(acc[mi][nj][2], acc[mi][nj][3]);
        }
}

// ==========================================================================
// Kernel S: sum Spart -> tf32-rounded fp32 g_S.  grid (16, 32).  PDL wait.
__global__ __launch_bounds__(256) void sconv() {
    GRIDDEP_WAIT();
    const int b = blockIdx.y, ds = blockIdx.x;
    const size_t base = (size_t)b * DD * DD + ds * 8 * DD;
    const int i = threadIdx.x;

    float4 s = make_float4(0.f, 0.f, 0.f, 0.f);
#pragma unroll
    for (int p = 0; p < NSPLIT; p++) {
        float4 v = *(const float4*)(g_Spart + (size_t)p * BB * DD * DD +
                                    base + i * 4);
        s.x += v.x; s.y += v.y; s.z += v.z; s.w += v.w;
    }
    float4 o;
    o.x = __uint_as_float(f2tf(s.x));
    o.y = __uint_as_float(f2tf(s.y));
    o.z = __uint_as_float(f2tf(s.z));
    o.w = __uint_as_float(f2tf(s.w));
    *(float4*)(g_S + base + i * 4) = o;
}

// ==========================================================================
// Kernel M: all-tf32 single-pass mid.  grid (8, 32), 512 threads.  (R16)
#define MID_SMEM_BYTES 203776
__global__ __launch_bounds__(512, 1) void mid_mma(const float* __restrict__ Wk,
                                                  const float* __restrict__ Wq,
                                                  const float* __restrict__ Wv) {
    extern __shared__ __align__(128) char sm[];
    uint32_t sb = smem_u32(sm);
    const int h = blockIdx.x, b = blockIdx.y;
    const int tid = threadIdx.x, lane = tid & 31, wid = tid >> 5;

    const uint32_t oS = sb, oWv = sb + 67584, oT1 = sb + 135168;
    const uint32_t oWk = sb + 168960, oWq = sb;
    float* fWv = (float*)(sm + 67584);
    float* fT1 = (float*)(sm + 135168);
    float* fWk = (float*)(sm + 168960);
    float* fT2 = (float*)(sm + 168960);
    float* fWq = (float*)sm;

    // PRE-WAIT prologue: Wk + Wv (independent of sconv)
    {
        const float* wk = Wk + (size_t)h * KQ * DD;
        for (int i = tid; i < 2048; i += 512) {
            int row = i >> 5, seg = i & 31;
            CP_ASYNC16(oWk + row * 528 + seg * 16, wk + (size_t)row * DD + seg * 4);
        }
        const float* wv = Wv + (size_t)h * DD * DD;
        for (int i = tid; i < 4096; i += 512) {
            int row = i >> 5, seg = i & 31;
            CP_ASYNC16(oWv + row * 528 + seg * 16, wv + (size_t)row * DD + seg * 4);
        }
        CP_ASYNC_COMMIT();
    }

    GRIDDEP_WAIT();   // sconv's g_S now visible

    // group 1: S (pre-rounded)
    {
        const float* sp = g_S + (size_t)b * DD * DD;
        for (int i = tid; i < 4096; i += 512) {
            int row = i >> 5, seg = i & 31;
            CP_ASYNC16(oS + row * 528 + seg * 16, sp + (size_t)row * DD + seg * 4);
        }
        CP_ASYNC_COMMIT();
    }

    const int a_row = lane & 15, a_cg = lane >> 4;
    const int b_row = (lane & 7) + ((lane >> 4) << 3);
    const int b_cg = (lane >> 3) & 1;
    const int g = lane >> 2, t = lane & 3;

    CP_ASYNC_WAIT0();   // Wk, Wv, S all landed
    __syncthreads();
    for (int i = tid; i < 2048; i += 512) {
        int row = i >> 5, seg = i & 31;
        float4 v = *(float4*)(fWk + row * 132 + seg * 4);
        v.x = __uint_as_float(f2tf(v.x));
        v.y = __uint_as_float(f2tf(v.y));
        v.z = __uint_as_float(f2tf(v.z));
        v.w = __uint_as_float(f2tf(v.w));
        *(float4*)(fWk + row * 132 + seg * 4) = v;
    }
    for (int i = tid; i < 4096; i += 512) {
        int row = i >> 5, seg = i & 31;
        float4 v = *(float4*)(fWv + row * 132 + seg * 4);
        v.x = __uint_as_float(f2tf(v.x));
        v.y = __uint_as_float(f2tf(v.y));
        v.z = __uint_as_float(f2tf(v.z));
        v.w = __uint_as_float(f2tf(v.w));
        *(float4*)(fWv + row * 132 + seg * 4) = v;
    }
    __syncthreads();

    // Stage 1: T1[64,128] = Wk @ S  (S symmetric)
    const int m0s = (wid & 3) * 16, n0s = (wid >> 2) * 32;
    {
        float acc1[4][4];
#pragma unroll
        for (int nj = 0; nj < 4; nj++)
#pragma unroll
            for (int q = 0; q < 4; q++) acc1[nj][q] = 0.f;
#pragma unroll
        for (int ko = 0; ko < 128; ko += 8) {
            uint32_t A[4], B[2][4];
            ldsm4(A, oWk + (m0s + a_row) * 528 + (ko + 4 * a_cg) * 4);
#pragma unroll
            for (int njp = 0; njp < 2; njp++)
                ldsm4(B[njp], oS + (n0s + njp * 16 + b_row) * 528 +
                              (ko + 4 * b_cg) * 4);
#pragma unroll
            for (int nj = 0; nj < 4; nj++)
                mma_tf32(acc1[nj], A,
                         B[nj >> 1][(nj & 1) * 2], B[nj >> 1][(nj & 1) * 2 + 1]);
        }
        __syncthreads();
#pragma unroll
        for (int nj = 0; nj < 4; nj++) {
            int cc = n0s + nj * 8 + t * 2;
            *(float2*)(fT1 + (m0s + g) * 132 + cc) =
                make_float2(__uint_as_float(f2tf(acc1[nj][0])),
                            __uint_as_float(f2tf(acc1[nj][1])));
            *(float2*)(fT1 + (m0s + g + 8) * 132 + cc) =
                make_float2(__uint_as_float(f2tf(acc1[nj][2])),
                            __uint_as_float(f2tf(acc1[nj][3])));
        }
    }
    // Wq into old-S slot
    {
        const float* wq = Wq + (size_t)h * KQ * DD;
        for (int i = tid; i < 2048; i += 512) {
            int row = i >> 5, seg = i & 31;
            CP_ASYNC16(oWq + row * 544 + seg * 16, wq + (size_t)row * DD + seg * 4);
        }
        CP_ASYNC_COMMIT();
    }
    __syncthreads();    // T1 visible

    // Stage 2: T2[64,128] = T1 @ Wv^T
    {
        float acc2[4][4];
#pragma unroll
        for (int nj = 0; nj < 4; nj++)
#pragma unroll
            for (int q = 0; q < 4; q++) acc2[nj][q] = 0.f;
#pragma unroll
        for (int ko = 0; ko < 128; ko += 8) {
            uint32_t A[4], B[2][4];
            ldsm4(A, oT1 + (m0s + a_row) * 528 + (ko + 4 * a_cg) * 4);
#pragma unroll
            for (int njp = 0; njp < 2; njp++)
                ldsm4(B[njp], oWv + (n0s + njp * 16 + b_row) * 528 +
                              (ko + 4 * b_cg) * 4);
#pragma unroll
            for (int nj = 0; nj < 4; nj++)
                mma_tf32(acc2[nj], A,
                         B[nj >> 1][(nj & 1) * 2], B[nj >> 1][(nj & 1) * 2 + 1]);
        }
        __syncthreads();
#pragma unroll
        for (int nj = 0; nj < 4; nj++) {
            int cc = n0s + nj * 8 + t * 2;
            *(float2*)(fT2 + (m0s + g) * 136 + cc) =
                make_float2(__uint_as_float(f2tf(acc2[nj][0])),
                            __uint_as_float(f2tf(acc2[nj][1])));
            *(float2*)(fT2 + (m0s + g + 8) * 136 + cc) =
                make_float2(__uint_as_float(f2tf(acc2[nj][2])),
                            __uint_as_float(f2tf(acc2[nj][3])));
        }
    }
    CP_ASYNC_WAIT0();   // Wq landed
    __syncthreads();
    for (int i = tid; i < 2048; i += 512) {
        int row = i >> 5, seg = i & 31;
        float4 v = *(float4*)(fWq + row * 136 + seg * 4);
        v.x = __uint_as_float(f2tf(v.x));
        v.y = __uint_as_float(f2tf(v.y));
        v.z = __uint_as_float(f2tf(v.z));
        v.w = __uint_as_float(f2tf(v.w));
        *(float4*)(fWq + row * 136 + seg * 4) = v;
    }
    __syncthreads();

    // Stage 3: M[128,128] = Wq^T @ T2.  Scalar-LDS fragments.
    const int m0 = (wid & 3) * 32, n0 = (wid >> 2) * 32;
    float acc3[2][4][4];
#pragma unroll
    for (int mi = 0; mi < 2; mi++)
#pragma unroll
        for (int nj = 0; nj < 4; nj++)
#pragma unroll
            for (int q = 0; q < 4; q++) acc3[mi][nj][q] = 0.f;
#pragma unroll
    for (int ko = 0; ko < 64; ko += 8) {
        uint32_t A[2][4];
#pragma unroll
        for (int mi = 0; mi < 2; mi++) {
            int m = m0 + mi * 16;
            A[mi][0] = __float_as_uint(fWq[(ko + t) * 136 + m + g]);
            A[mi][1] = __float_as_uint(fWq[(ko + t) * 136 + m + g + 8]);
            A[mi][2] = __float_as_uint(fWq[(ko + t + 4) * 136 + m + g]);
            A[mi][3] = __float_as_uint(fWq[(ko + t + 4) * 136 + m + g + 8]);
        }
        uint32_t B0[4], B1[4];
#pragma unroll
        for (int nj = 0; nj < 4; nj++) {
            int col = n0 + nj * 8 + g;
            B0[nj] = __float_as_uint(fT2[(ko + t) * 136 + col]);
            B1[nj] = __float_as_uint(fT2[(ko + t + 4) * 136 + col]);
        }
#pragma unroll
        for (int mi = 0; mi < 2; mi++)
#pragma unroll
            for (int nj = 0; nj < 4; nj++)
                mma_tf32(acc3[mi][nj], A[mi], B0[nj], B1[nj]);
    }
    float* Mp = g_Mpart + (size_t)(h * BB + b) * DD * DD;
#pragma unroll
    for (int mi = 0; mi < 2; mi++)
#pragma unroll
        for (int nj = 0; nj < 4; nj++) {
            int r = m0 + mi * 16 + g, cc = n0 + nj * 8 + t * 2;
            *(float2*)&Mp[r * DD + cc] =
                make_float2(acc3[mi][nj][0], acc3[mi][nj][1]);
            *(float2*)&Mp[(r + 8) * DD + cc] =
                make_float2(acc3[mi][nj][2], acc3[mi][nj][3]);
        }
}

// ==========================================================================
// Kernel C: sum Mparts -> tf32-rounded fp32 g_M.  grid (16, 32).  PDL wait.
__global__ __launch_bounds__(256) void mconv() {
    GRIDDEP_WAIT();
    const int b = blockIdx.y, ds = blockIdx.x;
    const size_t base = (size_t)b * DD * DD + ds * 8 * DD;
    const int i = threadIdx.x;

    float4 s = make_float4(0.f, 0.f, 0.f, 0.f);
#pragma unroll
    for (int h = 0; h < HH; h++) {
        float4 v = *(const float4*)(g_Mpart + (size_t)h * BB * DD * DD +
                                    base + i * 4);
        s.x += v.x; s.y += v.y; s.z += v.z; s.w += v.w;
    }
    float4 o;
    o.x = __uint_as_float(f2tf(s.x));
    o.y = __uint_as_float(f2tf(s.y));
    o.z = __uint_as_float(f2tf(s.z));
    o.w = __uint_as_float(f2tf(s.w));
    *(float4*)(g_M + base + i * 4) = o;
}

// ==========================================================================
// Kernel O: out = x @ M via tf32 mma, 64-row tiles, 2 CTAs/SM.  (R16)
#define OUT_SMEM_BYTES (33792 + 69632)   // 103424
__global__ __launch_bounds__(256, 2) void out_mma(const float* __restrict__ x,
                                                  float* __restrict__ out) {
    extern __shared__ __align__(128) char sm[];
    uint32_t sb = smem_u32(sm);
    const int b = blockIdx.y, nblk = blockIdx.x * 64;
    const int tid = threadIdx.x, lane = tid & 31, wid = tid >> 5;
    const int m0 = (wid & 1) * 32, n0 = (wid >> 1) * 32;

    const uint32_t tA = sb;            // x tile (64 rows)
    const uint32_t tB = sb + 33792;    // M tile
    float* tBf = (float*)(sm + 33792);

    // PRE-WAIT: x tile (independent of mconv)
    const float* xb = x + ((size_t)b * NN + nblk) * DD;
    for (int i = tid; i < 2048; i += 256) {
        int row = i >> 5, seg = i & 31;
        CP_ASYNC16(tA + row * 528 + seg * 16, xb + (size_t)row * DD + seg * 4);
    }
    CP_ASYNC_COMMIT();

    GRIDDEP_WAIT();   // mconv's g_M now visible

    // group 1: M tile
    {
        const float* mb = g_M + (size_t)b * DD * DD;
        for (int i = tid; i < 4096; i += 256) {
            int row = i >> 5, seg = i & 31;
            CP_ASYNC16(tB + row * 544 + seg * 16, mb + (size_t)row * DD + seg * 4);
        }
    }
    CP_ASYNC_COMMIT();

    CP_ASYNC_WAIT1();
    __syncthreads();
    // tf32-round x in place (overlaps M load)
    {
        float* tAf = (float*)sm;
        for (int i = tid; i < 2048; i += 256) {
            int row = i >> 5, seg = i & 31;
            float4 v = *(float4*)(tAf + row * 132 + seg * 4);
            v.x = __uint_as_float(f2tf(v.x));
            v.y = __uint_as_float(f2tf(v.y));
            v.z = __uint_as_float(f2tf(v.z));
            v.w = __uint_as_float(f2tf(v.w));
            *(float4*)(tAf + row * 132 + seg * 4) = v;
        }
    }
    CP_ASYNC_WAIT0();
    __syncthreads();

    float acc[2][4][4];
#pragma unroll
    for (int mi = 0; mi < 2; mi++)
#pragma unroll
        for (int nj = 0; nj < 4; nj++)
#pragma unroll
            for (int q = 0; q < 4; q++) acc[mi][nj][q] = 0.f;

    const int a_row = lane & 15, a_cg = lane >> 4;
    const int g = lane >> 2, t = lane & 3;

#pragma unroll
    for (int ko = 0; ko < 128; ko += 8) {
        uint32_t A[2][4];
#pragma unroll
        for (int mi = 0; mi < 2; mi++)
            ldsm4(A[mi], tA + (m0 + mi * 16 + a_row) * 528 +
                         (ko + 4 * a_cg) * 4);
        uint32_t B0[4], B1[4];
#pragma unroll
        for (int nj = 0; nj < 4; nj++) {
            int col = n0 + nj * 8 + g;
            B0[nj] = __float_as_uint(tBf[(ko + t) * 136 + col]);
            B1[nj] = __float_as_uint(tBf[(ko + t + 4) * 136 + col]);
        }
#pragma unroll
        for (int mi = 0; mi < 2; mi++)
#pragma unroll
            for (int nj = 0; nj < 4; nj++)
                mma_tf32(acc[mi][nj], A[mi], B0[nj], B1[nj]);
    }

    float* ob = out + ((size_t)b * NN + nblk) * DD;
#pragma unroll
    for (int mi = 0; mi < 2; mi++)
#pragma unroll
        for (int nj = 0; nj < 4; nj++) {
            int r = m0 + mi * 16 + g, cc = n0 + nj * 8 + t * 2;
            *(float2*)&ob[r * DD + cc] =
                make_float2(acc[mi][nj][0], acc[mi][nj][1]);
            *(float2*)&ob[(r + 8) * DD + cc] =
                make_float2(acc[mi][nj][2], acc[mi][nj][3]);
        }
}

// ==========================================================================
extern "C" void kernel_launch(void* const* d_in, const int* in_sizes, int n_in,
                              void* d_out, int out_size) {
    const float* x  = (const float*)d_in[0];  // [32, 2048, 128]
    const float* Wk = (const float*)d_in[1];  // [8, 64, 128]
    const float* Wq = (const float*)d_in[2];  // [8, 64, 128]
    const float* Wv = (const float*)d_in[3];  // [8, 128, 128]
    float* out = (float*)d_out;               // [32, 2048, 128]

    cudaFuncSetAttribute(gram_mma, cudaFuncAttributeMaxDynamicSharedMemorySize,
                         GRAM_SMEM_BYTES);
    cudaFuncSetAttribute(mid_mma, cudaFuncAttributeMaxDynamicSharedMemorySize,
                         MID_SMEM_BYTES);
    cudaFuncSetAttribute(out_mma, cudaFuncAttributeMaxDynamicSharedMemorySize,
                         OUT_SMEM_BYTES);

    cudaLaunchAttribute pdl[1];
    pdl[0].id = cudaLaunchAttributeProgrammaticStreamSerialization;
    pdl[0].val.programmaticStreamSerializationAllowed = 1;

    {   // gram (PDL — no upstream data dependency; overlaps prior replay tail)
        cudaLaunchConfig_t cfg = {};
        cfg.gridDim = dim3(NSPLIT, 32); cfg.blockDim = dim3(256);
        cfg.dynamicSmemBytes = GRAM_SMEM_BYTES; cfg.stream = 0;
        cfg.attrs = pdl; cfg.numAttrs = 1;
        cudaLaunchKernelEx(&cfg, gram_mma, x);
    }
    {   // sconv (PDL)
        cudaLaunchConfig_t cfg = {};
        cfg.gridDim = dim3(16, 32); cfg.blockDim = dim3(256);
        cfg.dynamicSmemBytes = 0; cfg.stream = 0;
        cfg.attrs = pdl; cfg.numAttrs = 1;
        cudaLaunchKernelEx(&cfg, sconv);
    }
    {   // mid (PDL)
        cudaLaunchConfig_t cfg = {};
        cfg.gridDim = dim3(HH, 32); cfg.blockDim = dim3(512);
        cfg.dynamicSmemBytes = MID_SMEM_BYTES; cfg.stream = 0;
        cfg.attrs = pdl; cfg.numAttrs = 1;
        cudaLaunchKernelEx(&cfg, mid_mma, Wk, Wq, Wv);
    }
    {   // mconv (PDL)
        cudaLaunchConfig_t cfg = {};
        cfg.gridDim = dim3(16, 32); cfg.blockDim = dim3(256);
        cfg.dynamicSmemBytes = 0; cfg.stream = 0;
        cfg.attrs = pdl; cfg.numAttrs = 1;
        cudaLaunchKernelEx(&cfg, mconv);
    }
    {   // out (PDL)
        cudaLaunchConfig_t cfg = {};
        cfg.gridDim = dim3(32, 32); cfg.blockDim = dim3(256);
        cfg.dynamicSmemBytes = OUT_SMEM_BYTES; cfg.stream = 0;
        cfg.attrs = pdl; cfg.numAttrs = 1;
        cudaLaunchKernelEx(&cfg, out_mma, x, out);
    }
}